// round 1
// baseline (speedup 1.0000x reference)
#include <cuda_runtime.h>
#include <math.h>

#define BATCH 4
#define SEQ   2048
#define EMD   768
#define HEADS 8
#define HDIM  96
#define MROWS (BATCH*SEQ)

#define TQ 16
#define TK 16
#define KSTR 772   // padded smem row stride (floats), float4-aligned
#define SQRT_EMD 27.712812921102035f

// Scratch (allocation-free rule: __device__ globals)
__device__ float g_Q[MROWS*EMD];
__device__ float g_K[MROWS*EMD];
__device__ float g_V[MROWS*EMD];
__device__ float g_O[MROWS*EMD];

// ---------------------------------------------------------------------------
// GEMM: C[m,n] = sum_k A[m,k] * W[n,k] + bias[n]
// A: [M,768] row-major, W: [768,768] row-major (out,in) -> NT layout
// 128x128 tile, BK=8, 256 threads, 8x8 per-thread microtile.
// blockIdx.z selects one of up to 3 (W, bias, C) triples (fused QKV).
// ---------------------------------------------------------------------------
__global__ __launch_bounds__(256)
void gemm_nt_bias(const float* __restrict__ A,
                  const float* __restrict__ W0, const float* __restrict__ b0, float* __restrict__ C0,
                  const float* __restrict__ W1, const float* __restrict__ b1, float* __restrict__ C1,
                  const float* __restrict__ W2, const float* __restrict__ b2, float* __restrict__ C2)
{
    const float* W    = W0;
    const float* bias = b0;
    float*       C    = C0;
    if (blockIdx.z == 1) { W = W1; bias = b1; C = C1; }
    if (blockIdx.z == 2) { W = W2; bias = b2; C = C2; }

    __shared__ float As[8][128];
    __shared__ float Bs[8][128];

    const int tid = threadIdx.x;
    const int tx  = tid & 15;
    const int ty  = tid >> 4;
    const int m0  = blockIdx.x * 128;
    const int n0  = blockIdx.y * 128;

    const int lr = tid >> 1;        // 0..127: tile row for loading
    const int lc = (tid & 1) * 4;   // 0 or 4: k sub-offset (float4)

    const float* Ap = A + (size_t)(m0 + lr) * EMD + lc;
    const float* Wp = W + (size_t)(n0 + lr) * EMD + lc;

    float acc[8][8];
    #pragma unroll
    for (int i = 0; i < 8; i++)
        #pragma unroll
        for (int j = 0; j < 8; j++) acc[i][j] = 0.f;

    for (int k0 = 0; k0 < EMD; k0 += 8) {
        float4 av = *(const float4*)(Ap + k0);
        float4 wv = *(const float4*)(Wp + k0);
        As[lc+0][lr] = av.x; As[lc+1][lr] = av.y; As[lc+2][lr] = av.z; As[lc+3][lr] = av.w;
        Bs[lc+0][lr] = wv.x; Bs[lc+1][lr] = wv.y; Bs[lc+2][lr] = wv.z; Bs[lc+3][lr] = wv.w;
        __syncthreads();

        #pragma unroll
        for (int k = 0; k < 8; k++) {
            float a[8], bb[8];
            #pragma unroll
            for (int i = 0; i < 8; i++) a[i]  = As[k][ty*8 + i];
            #pragma unroll
            for (int j = 0; j < 8; j++) bb[j] = Bs[k][tx*8 + j];
            #pragma unroll
            for (int i = 0; i < 8; i++)
                #pragma unroll
                for (int j = 0; j < 8; j++) acc[i][j] += a[i] * bb[j];
        }
        __syncthreads();
    }

    #pragma unroll
    for (int i = 0; i < 8; i++) {
        const int m = m0 + ty*8 + i;
        #pragma unroll
        for (int j = 0; j < 8; j += 4) {
            const int n = n0 + tx*8 + j;
            float4 o;
            o.x = acc[i][j+0] + bias[n+0];
            o.y = acc[i][j+1] + bias[n+1];
            o.z = acc[i][j+2] + bias[n+2];
            o.w = acc[i][j+3] + bias[n+3];
            *(float4*)(C + (size_t)m * EMD + n) = o;
        }
    }
}

// ---------------------------------------------------------------------------
// Fused attention with softmax over the HEADS axis.
// CTA: (b, q-tile of 16). 8 warps, warp = head. Streams k in tiles of 16.
// Per tile:  E_h = Q_h K_h^T  (per warp, regs)
//            exp(E) -> smem, denom = sum over heads, normalize in place
//            O_h += A_h V_h   (48 fp32 accumulators per lane)
// No k-coupling: softmax is per (q,k) column across heads only.
// ---------------------------------------------------------------------------
__global__ __launch_bounds__(256)
void attn_kernel()
{
    extern __shared__ float sm[];
    float* Qs = sm;                       // TQ * KSTR
    float* Ks = Qs + TQ*KSTR;             // TK * KSTR
    float* Vs = Ks + TK*KSTR;             // TK * KSTR
    float* Es = Vs + TK*KSTR;             // HEADS * TQ * 17

    const int b    = blockIdx.y;
    const int q0   = blockIdx.x * TQ;
    const int tid  = threadIdx.x;
    const int warp = tid >> 5;            // head index
    const int lane = tid & 31;
    const int qg   = lane >> 3;           // 0..3 : q sub-rows qg*4 .. qg*4+3
    const int kg   = lane & 7;            // 0..7 : k cols {kg, kg+8}; d group in O phase
    const int hb   = warp * HDIM;

    // Load Q tile (16 rows x 768 floats, all heads)
    for (int j = tid; j < TQ*(EMD/4); j += 256) {
        const int r = j / (EMD/4);
        const int c = (j % (EMD/4)) * 4;
        *(float4*)(Qs + r*KSTR + c) =
            *(const float4*)(g_Q + (size_t)(b*SEQ + q0 + r)*EMD + c);
    }

    float Oacc[48];
    #pragma unroll
    for (int i = 0; i < 48; i++) Oacc[i] = 0.f;

    for (int k0 = 0; k0 < SEQ; k0 += TK) {
        __syncthreads();   // previous iteration's reads of Ks/Vs/Es complete

        // Cooperative load of K and V tiles (16 rows x 768 floats each)
        for (int j = tid; j < TK*(EMD/4); j += 256) {
            const int r = j / (EMD/4);
            const int c = (j % (EMD/4)) * 4;
            const size_t g = (size_t)(b*SEQ + k0 + r)*EMD + c;
            *(float4*)(Ks + r*KSTR + c) = *(const float4*)(g_K + g);
            *(float4*)(Vs + r*KSTR + c) = *(const float4*)(g_V + g);
        }
        __syncthreads();

        // ---- Energy: E[q][k] for this head, 4q x 2k per lane ----
        float e[4][2] = {{0.f,0.f},{0.f,0.f},{0.f,0.f},{0.f,0.f}};
        #pragma unroll
        for (int d = 0; d < HDIM; d += 4) {
            const float* qb = Qs + hb + d;
            const float* kb = Ks + hb + d;
            const float4 k0v = *(const float4*)(kb + (size_t)kg      * KSTR);
            const float4 k1v = *(const float4*)(kb + (size_t)(kg + 8)* KSTR);
            #pragma unroll
            for (int i = 0; i < 4; i++) {
                const float4 qv = *(const float4*)(qb + (size_t)(qg*4 + i) * KSTR);
                e[i][0] += qv.x*k0v.x + qv.y*k0v.y + qv.z*k0v.z + qv.w*k0v.w;
                e[i][1] += qv.x*k1v.x + qv.y*k1v.y + qv.z*k1v.z + qv.w*k1v.w;
            }
        }

        // exp -> smem (per-head tile, row stride 17 to dodge conflicts)
        #pragma unroll
        for (int i = 0; i < 4; i++) {
            Es[(warp*TQ + qg*4 + i)*17 + kg    ] = __expf(e[i][0]);
            Es[(warp*TQ + qg*4 + i)*17 + kg + 8] = __expf(e[i][1]);
        }
        __syncthreads();

        // Cross-head denominator + in-place normalize: thread -> one (q,k)
        {
            const int q = tid >> 4;
            const int k = tid & 15;
            float s = 0.f;
            #pragma unroll
            for (int h = 0; h < HEADS; h++) s += Es[(h*TQ + q)*17 + k];
            const float inv = 1.0f / (s * SQRT_EMD);
            #pragma unroll
            for (int h = 0; h < HEADS; h++) Es[(h*TQ + q)*17 + k] *= inv;
        }
        __syncthreads();

        // ---- O += A @ V : lane handles 4 q-rows x 12 d-cols ----
        #pragma unroll
        for (int k = 0; k < TK; k++) {
            float a[4];
            #pragma unroll
            for (int i = 0; i < 4; i++)
                a[i] = Es[(warp*TQ + qg*4 + i)*17 + k];

            const float* vp = Vs + (size_t)k*KSTR + hb + kg*12;
            const float4 v0 = *(const float4*)(vp + 0);
            const float4 v1 = *(const float4*)(vp + 4);
            const float4 v2 = *(const float4*)(vp + 8);
            float v[12];
            v[0]=v0.x; v[1]=v0.y; v[2]=v0.z;  v[3]=v0.w;
            v[4]=v1.x; v[5]=v1.y; v[6]=v1.z;  v[7]=v1.w;
            v[8]=v2.x; v[9]=v2.y; v[10]=v2.z; v[11]=v2.w;

            #pragma unroll
            for (int i = 0; i < 4; i++)
                #pragma unroll
                for (int c = 0; c < 12; c++)
                    Oacc[i*12 + c] += a[i] * v[c];
        }
    }

    // Write O in [M, 768] layout (e = h*96 + d), ready for the out-projection
    #pragma unroll
    for (int i = 0; i < 4; i++) {
        float* op = g_O + (size_t)(b*SEQ + q0 + qg*4 + i)*EMD + hb + kg*12;
        float4 o0, o1, o2;
        o0.x=Oacc[i*12+0]; o0.y=Oacc[i*12+1]; o0.z=Oacc[i*12+2];  o0.w=Oacc[i*12+3];
        o1.x=Oacc[i*12+4]; o1.y=Oacc[i*12+5]; o1.z=Oacc[i*12+6];  o1.w=Oacc[i*12+7];
        o2.x=Oacc[i*12+8]; o2.y=Oacc[i*12+9]; o2.z=Oacc[i*12+10]; o2.w=Oacc[i*12+11];
        *(float4*)(op + 0) = o0;
        *(float4*)(op + 4) = o1;
        *(float4*)(op + 8) = o2;
    }
}

// ---------------------------------------------------------------------------
extern "C" void kernel_launch(void* const* d_in, const int* in_sizes, int n_in,
                              void* d_out, int out_size)
{
    const float* x  = (const float*)d_in[0];
    const float* Wq = (const float*)d_in[1];
    const float* bq = (const float*)d_in[2];
    const float* Wk = (const float*)d_in[3];
    const float* bk = (const float*)d_in[4];
    const float* Wv = (const float*)d_in[5];
    const float* bv = (const float*)d_in[6];
    const float* Wo = (const float*)d_in[7];
    const float* bo = (const float*)d_in[8];
    float* out = (float*)d_out;

    float *Qp, *Kp, *Vp, *Op;
    cudaGetSymbolAddress((void**)&Qp, g_Q);
    cudaGetSymbolAddress((void**)&Kp, g_K);
    cudaGetSymbolAddress((void**)&Vp, g_V);
    cudaGetSymbolAddress((void**)&Op, g_O);

    const int smem_bytes = (3*TQ*KSTR + HEADS*TQ*17) * (int)sizeof(float); // 156928
    cudaFuncSetAttribute(attn_kernel, cudaFuncAttributeMaxDynamicSharedMemorySize, smem_bytes);

    // 1) Fused QKV projections (z selects Q/K/V)
    gemm_nt_bias<<<dim3(MROWS/128, EMD/128, 3), 256>>>(
        x, Wq, bq, Qp, Wk, bk, Kp, Wv, bv, Vp);

    // 2) Fused head-axis-softmax attention
    attn_kernel<<<dim3(SEQ/TQ, BATCH), 256, smem_bytes>>>();

    // 3) Output projection -> d_out
    gemm_nt_bias<<<dim3(MROWS/128, EMD/128, 1), 256>>>(
        Op, Wo, bo, out, Wo, bo, out, Wo, bo, out);
}

// round 3
// speedup vs baseline: 1.9808x; 1.9808x over previous
#include <cuda_runtime.h>
#include <math.h>

#define BATCH 4
#define SEQ   2048
#define EMD   768
#define HEADS 8
#define HDIM  96
#define MROWS (BATCH*SEQ)

#define TQ 32
#define TK 16
#define KSTR 772           // smem row stride (floats): 772*4B = 3088B, 16B-aligned
#define ESTR 17
#define SQRT_EMD 27.712812921102035f

typedef unsigned long long ull;

__device__ __forceinline__ ull pk2(float lo, float hi) {
    ull r; asm("mov.b64 %0,{%1,%2};" : "=l"(r) : "f"(lo), "f"(hi)); return r;
}
__device__ __forceinline__ void upk2(ull v, float& lo, float& hi) {
    asm("mov.b64 {%0,%1},%2;" : "=f"(lo), "=f"(hi) : "l"(v));
}
#define FFMA2(d,a,b,c) asm("fma.rn.f32x2 %0,%1,%2,%3;" : "=l"(d) : "l"(a), "l"(b), "l"(c))

// Scratch (allocation-free rule: __device__ globals)
__device__ float g_Q[MROWS*EMD];
__device__ float g_K[MROWS*EMD];
__device__ float g_V[MROWS*EMD];
__device__ float g_O[MROWS*EMD];

// ---------------------------------------------------------------------------
// GEMM: C[m,n] = sum_k A[m,k] * W[n,k] + bias[n]   (NT, fp32, FFMA2 core)
// 128x128 tile, BK=8, 256 threads, 8x8 microtile as 8x4 f32x2 pairs.
// B smem uses additive swizzle c' = c + 2*(c>>5) -> conflict-free ull loads.
// blockIdx.z selects one of up to 3 (W, bias, C) triples (fused QKV).
// ---------------------------------------------------------------------------
__global__ __launch_bounds__(256)
void gemm_nt_bias(const float* __restrict__ A,
                  const float* __restrict__ W0, const float* __restrict__ bv0, float* __restrict__ C0,
                  const float* __restrict__ W1, const float* __restrict__ bv1, float* __restrict__ C1,
                  const float* __restrict__ W2, const float* __restrict__ bv2, float* __restrict__ C2)
{
    const float* W    = W0;
    const float* bias = bv0;
    float*       C    = C0;
    if (blockIdx.z == 1) { W = W1; bias = bv1; C = C1; }
    if (blockIdx.z == 2) { W = W2; bias = bv2; C = C2; }

    __shared__ __align__(16) float As[8][128];
    __shared__ __align__(16) float Bs[8][136];   // 128 cols + swizzle headroom

    const int tid = threadIdx.x;
    const int tx  = tid & 15;
    const int ty  = tid >> 4;
    const int m0  = blockIdx.x * 128;
    const int n0  = blockIdx.y * 128;

    const int lr = tid >> 1;        // 0..127: tile row for loading
    const int lc = (tid & 1) * 4;   // 0 or 4: k sub-offset (float4)
    const int bc = lr + ((lr >> 5) << 1);   // swizzled B column for store
    const int txc = tx*8 + ((tx >> 2) << 1); // swizzled B column for frag load

    const float* Ap = A + (size_t)(m0 + lr) * EMD + lc;
    const float* Wp = W + (size_t)(n0 + lr) * EMD + lc;

    ull acc[8][4];
    #pragma unroll
    for (int i = 0; i < 8; i++)
        #pragma unroll
        for (int j = 0; j < 4; j++) acc[i][j] = 0ull;

    for (int k0 = 0; k0 < EMD; k0 += 8) {
        float4 av = *(const float4*)(Ap + k0);
        float4 wv = *(const float4*)(Wp + k0);
        As[lc+0][lr] = av.x; As[lc+1][lr] = av.y; As[lc+2][lr] = av.z; As[lc+3][lr] = av.w;
        Bs[lc+0][bc] = wv.x; Bs[lc+1][bc] = wv.y; Bs[lc+2][bc] = wv.z; Bs[lc+3][bc] = wv.w;
        __syncthreads();

        #pragma unroll
        for (int k = 0; k < 8; k++) {
            const float4 a03 = *(const float4*)&As[k][ty*8];
            const float4 a47 = *(const float4*)&As[k][ty*8 + 4];
            ull a2[8];
            a2[0] = pk2(a03.x, a03.x); a2[1] = pk2(a03.y, a03.y);
            a2[2] = pk2(a03.z, a03.z); a2[3] = pk2(a03.w, a03.w);
            a2[4] = pk2(a47.x, a47.x); a2[5] = pk2(a47.y, a47.y);
            a2[6] = pk2(a47.z, a47.z); a2[7] = pk2(a47.w, a47.w);
            const ull* bp = (const ull*)&Bs[k][txc];
            const ull bb0 = bp[0], bb1 = bp[1], bb2 = bp[2], bb3 = bp[3];
            #pragma unroll
            for (int i = 0; i < 8; i++) {
                FFMA2(acc[i][0], a2[i], bb0, acc[i][0]);
                FFMA2(acc[i][1], a2[i], bb1, acc[i][1]);
                FFMA2(acc[i][2], a2[i], bb2, acc[i][2]);
                FFMA2(acc[i][3], a2[i], bb3, acc[i][3]);
            }
        }
        __syncthreads();
    }

    const float4 bi0 = *(const float4*)&bias[n0 + tx*8];
    const float4 bi1 = *(const float4*)&bias[n0 + tx*8 + 4];
    #pragma unroll
    for (int i = 0; i < 8; i++) {
        const int m = m0 + ty*8 + i;
        float c0,c1,c2,c3,c4,c5,c6,c7;
        upk2(acc[i][0], c0, c1); upk2(acc[i][1], c2, c3);
        upk2(acc[i][2], c4, c5); upk2(acc[i][3], c6, c7);
        float4 o0, o1;
        o0.x = c0 + bi0.x; o0.y = c1 + bi0.y; o0.z = c2 + bi0.z; o0.w = c3 + bi0.w;
        o1.x = c4 + bi1.x; o1.y = c5 + bi1.y; o1.z = c6 + bi1.z; o1.w = c7 + bi1.w;
        *(float4*)(C + (size_t)m * EMD + n0 + tx*8    ) = o0;
        *(float4*)(C + (size_t)m * EMD + n0 + tx*8 + 4) = o1;
    }
}

// ---------------------------------------------------------------------------
// Fused attention, softmax over HEADS axis. FFMA2 core.
// CTA: (b, 32-row q-tile). 8 warps = 1 per head. k streamed in tiles of 16.
// Lane (qg = lane>>3 in 0..3, kg = lane&7): rows {qg+4i}, k-cols {kg, kg+8},
// d-cols kg*12..+11 in the AV phase.
// ---------------------------------------------------------------------------
__global__ __launch_bounds__(256)
void attn_kernel()
{
    extern __shared__ float sm[];
    float* Qs = sm;                       // TQ * KSTR
    float* Ks = Qs + TQ*KSTR;             // TK * KSTR
    float* Vs = Ks + TK*KSTR;             // TK * KSTR
    float* Es = Vs + TK*KSTR;             // HEADS * TQ * ESTR

    const int b    = blockIdx.y;
    const int q0   = blockIdx.x * TQ;
    const int tid  = threadIdx.x;
    const int warp = tid >> 5;            // head index
    const int lane = tid & 31;
    const int qg   = lane >> 3;           // 0..3
    const int kg   = lane & 7;            // 0..7
    const int hb   = warp * HDIM;

    // Load Q tile (32 rows x 768 floats, all heads)
    for (int j = tid; j < TQ*(EMD/4); j += 256) {
        const int r = j / (EMD/4);
        const int c = (j % (EMD/4)) * 4;
        *(float4*)(Qs + r*KSTR + c) =
            *(const float4*)(g_Q + (size_t)(b*SEQ + q0 + r)*EMD + c);
    }

    ull Oacc[8][6];
    #pragma unroll
    for (int i = 0; i < 8; i++)
        #pragma unroll
        for (int j = 0; j < 6; j++) Oacc[i][j] = 0ull;

    for (int k0 = 0; k0 < SEQ; k0 += TK) {
        __syncthreads();   // previous iteration's reads of Ks/Vs/Es complete
                           // (also orders the Q-tile stores before first use)

        for (int j = tid; j < TK*(EMD/4); j += 256) {
            const int r = j / (EMD/4);
            const int c = (j % (EMD/4)) * 4;
            const size_t g = (size_t)(b*SEQ + k0 + r)*EMD + c;
            *(float4*)(Ks + r*KSTR + c) = *(const float4*)(g_K + g);
            *(float4*)(Vs + r*KSTR + c) = *(const float4*)(g_V + g);
        }
        __syncthreads();

        // ---- Energy: rows qg+4i (i=0..7), k-cols {kg, kg+8} ----
        ull e2[8][2];
        #pragma unroll
        for (int i = 0; i < 8; i++) { e2[i][0] = 0ull; e2[i][1] = 0ull; }

        const float* qbase  = Qs + (size_t)qg*KSTR + hb;
        const float* k0base = Ks + (size_t)kg*KSTR + hb;
        const float* k1base = Ks + (size_t)(kg+8)*KSTR + hb;

        #pragma unroll
        for (int d = 0; d < HDIM; d += 4) {
            const ulonglong2 kv0 = *(const ulonglong2*)(k0base + d);
            const ulonglong2 kv1 = *(const ulonglong2*)(k1base + d);
            #pragma unroll
            for (int i = 0; i < 8; i++) {
                const ulonglong2 qv = *(const ulonglong2*)(qbase + (size_t)(4*i)*KSTR + d);
                FFMA2(e2[i][0], qv.x, kv0.x, e2[i][0]);
                FFMA2(e2[i][0], qv.y, kv0.y, e2[i][0]);
                FFMA2(e2[i][1], qv.x, kv1.x, e2[i][1]);
                FFMA2(e2[i][1], qv.y, kv1.y, e2[i][1]);
            }
        }

        // exp -> Es
        #pragma unroll
        for (int i = 0; i < 8; i++) {
            float lo, hi;
            upk2(e2[i][0], lo, hi); const float s0 = lo + hi;
            upk2(e2[i][1], lo, hi); const float s1 = lo + hi;
            const int row = warp*TQ + qg + 4*i;
            Es[row*ESTR + kg    ] = __expf(s0);
            Es[row*ESTR + kg + 8] = __expf(s1);
        }
        __syncthreads();

        // Cross-head denominator + in-place normalize: 2 (q,k) pairs / thread
        #pragma unroll
        for (int pp = 0; pp < 2; pp++) {
            const int p = tid*2 + pp;
            const int q = p >> 4;
            const int k = p & 15;
            float s = 0.f;
            #pragma unroll
            for (int h = 0; h < HEADS; h++) s += Es[(h*TQ + q)*ESTR + k];
            const float inv = 1.0f / (s * SQRT_EMD);
            #pragma unroll
            for (int h = 0; h < HEADS; h++) Es[(h*TQ + q)*ESTR + k] *= inv;
        }
        __syncthreads();

        // ---- O += A @ V : rows qg+4i, d-cols kg*12..+11 ----
        #pragma unroll
        for (int k = 0; k < TK; k++) {
            ull a2[8];
            #pragma unroll
            for (int i = 0; i < 8; i++) {
                const float av = Es[(warp*TQ + qg + 4*i)*ESTR + k];
                a2[i] = pk2(av, av);
            }
            const float* vp = Vs + (size_t)k*KSTR + hb + kg*12;
            const ulonglong2 v0 = *(const ulonglong2*)(vp + 0);
            const ulonglong2 v1 = *(const ulonglong2*)(vp + 4);
            const ulonglong2 v2 = *(const ulonglong2*)(vp + 8);
            #pragma unroll
            for (int i = 0; i < 8; i++) {
                FFMA2(Oacc[i][0], a2[i], v0.x, Oacc[i][0]);
                FFMA2(Oacc[i][1], a2[i], v0.y, Oacc[i][1]);
                FFMA2(Oacc[i][2], a2[i], v1.x, Oacc[i][2]);
                FFMA2(Oacc[i][3], a2[i], v1.y, Oacc[i][3]);
                FFMA2(Oacc[i][4], a2[i], v2.x, Oacc[i][4]);
                FFMA2(Oacc[i][5], a2[i], v2.y, Oacc[i][5]);
            }
        }
    }

    // Write O in [M, 768] layout (col = h*96 + d)
    #pragma unroll
    for (int i = 0; i < 8; i++) {
        float* op = g_O + (size_t)(b*SEQ + q0 + qg + 4*i)*EMD + hb + kg*12;
        float f[12];
        upk2(Oacc[i][0], f[0], f[1]);  upk2(Oacc[i][1], f[2],  f[3]);
        upk2(Oacc[i][2], f[4], f[5]);  upk2(Oacc[i][3], f[6],  f[7]);
        upk2(Oacc[i][4], f[8], f[9]);  upk2(Oacc[i][5], f[10], f[11]);
        float4 o0, o1, o2;
        o0.x=f[0]; o0.y=f[1]; o0.z=f[2];  o0.w=f[3];
        o1.x=f[4]; o1.y=f[5]; o1.z=f[6];  o1.w=f[7];
        o2.x=f[8]; o2.y=f[9]; o2.z=f[10]; o2.w=f[11];
        *(float4*)(op + 0) = o0;
        *(float4*)(op + 4) = o1;
        *(float4*)(op + 8) = o2;
    }
}

// ---------------------------------------------------------------------------
extern "C" void kernel_launch(void* const* d_in, const int* in_sizes, int n_in,
                              void* d_out, int out_size)
{
    const float* x  = (const float*)d_in[0];
    const float* Wq = (const float*)d_in[1];
    const float* bq = (const float*)d_in[2];
    const float* Wk = (const float*)d_in[3];
    const float* bk = (const float*)d_in[4];
    const float* Wv = (const float*)d_in[5];
    const float* bv = (const float*)d_in[6];
    const float* Wo = (const float*)d_in[7];
    const float* bo = (const float*)d_in[8];
    float* out = (float*)d_out;

    float *Qp, *Kp, *Vp, *Op;
    cudaGetSymbolAddress((void**)&Qp, g_Q);
    cudaGetSymbolAddress((void**)&Kp, g_K);
    cudaGetSymbolAddress((void**)&Vp, g_V);
    cudaGetSymbolAddress((void**)&Op, g_O);

    const int smem_bytes = ((TQ + 2*TK)*KSTR + HEADS*TQ*ESTR) * (int)sizeof(float); // 215040
    cudaFuncSetAttribute(attn_kernel, cudaFuncAttributeMaxDynamicSharedMemorySize, smem_bytes);

    // 1) Fused QKV projections (z selects Q/K/V)
    gemm_nt_bias<<<dim3(MROWS/128, EMD/128, 3), 256>>>(
        x, Wq, bq, Qp, Wk, bk, Kp, Wv, bv, Vp);

    // 2) Fused head-axis-softmax attention
    attn_kernel<<<dim3(SEQ/TQ, BATCH), 256, smem_bytes>>>();

    // 3) Output projection -> d_out
    gemm_nt_bias<<<dim3(MROWS/128, EMD/128, 1), 256>>>(
        Op, Wo, bo, out, Wo, bo, out, Wo, bo, out);
}